// round 14
// baseline (speedup 1.0000x reference)
#include <cuda_runtime.h>
#include <math.h>

// Problem constants (fixed by the dataset)
#define TT      128
#define TT2     64
#define NCH     1536
#define NC0     10000
#define NCROSS  30000
#define NE      120000
#define DEGCAP  32            // P(Poisson(4) > 32) ~ 1e-22; safe fixed bucket
#define L2E     1.44269504088896f
#define SCATB   ((NE + 255) / 256)           // 469 scatter blocks (1 edge/thread)
#define SDQB    (NCROSS / 4)                 // 7500 sdq blocks (4 nodes/block)

// ---------------- scratch (static device allocations) ----------------
__device__ float4 g_sq4[NCROSS * TT2];     // [n][tp] = (s0,q0,s1,q1), s log2e-scaled
__device__ int    g_cnt[NCROSS];
__device__ int    g_csr[NCROSS * DEGCAP];  // entries pre-multiplied by TT2

// W rows (13x4 row-major): 0 sigA, 1 wireA, 2 chanA, 3 zero, 4 planeA,
// 5 sigB, 6 wireB, 7 chanB, 8 zero, 9 planeB, 10 ray_x, 11 ray_y, 12 tick
// coefs out[10]: sA sB sT dA dB dT qA qB qT bm   (s,d scaled by log2e)
__device__ __forceinline__ void calc_coefs(
    const float* __restrict__ W, const float* __restrict__ asrc,
    const float* __restrict__ adst, const float* __restrict__ Wm,
    const float* __restrict__ bm, float* out)
{
    float sA = 0, sB = 0, sT = 0, dA = 0, dB = 0, dT = 0, qA = 0, qB = 0, qT = 0;
#pragma unroll
    for (int o = 0; o < 4; o++) {
        float wA = W[o], wB = W[20 + o], wT = W[48 + o];
        sA += wA * asrc[o]; sB += wB * asrc[o]; sT += wT * asrc[o];
        dA += wA * adst[o]; dB += wB * adst[o]; dT += wT * adst[o];
        qA += wA * Wm[o];   qB += wB * Wm[o];   qT += wT * Wm[o];
    }
    out[0] = sA * L2E; out[1] = sB * L2E; out[2] = sT * L2E;
    out[3] = dA * L2E; out[4] = dB * L2E; out[5] = dT * L2E;
    out[6] = qA; out[7] = qB; out[8] = qT; out[9] = bm[0];
}

// Per-node static bases (sb, db scaled by log2e) + channels.
__device__ __forceinline__ void node_static(
    int i,
    const int* __restrict__ c0, const int* __restrict__ c1, const int* __restrict__ c2,
    const int* __restrict__ g01, const int* __restrict__ g12, const int* __restrict__ g20,
    const float* __restrict__ r01, const float* __restrict__ r12, const float* __restrict__ r20,
    const float* __restrict__ W, const float* __restrict__ bg,
    const float* __restrict__ asrc, const float* __restrict__ adst,
    const float* __restrict__ Wm,
    float* sb_o, float* db_o, float* qb_o, int* chA_o, int* chB_o)
{
    int p = i / NC0, c = i % NC0;
    const int* g; const float* r; const int* cA; const int* cB; float pA, pB;
    if (p == 0)      { g = g01; r = r01; cA = c0; cB = c1; pA = 0.f; pB = 1.f; }
    else if (p == 1) { g = g12; r = r12; cA = c1; cB = c2; pA = 1.f; pB = 2.f; }
    else             { g = g20; r = r20; cA = c2; cB = c0; pA = 2.f; pB = 0.f; }
    int wA = g[2 * c], wB = g[2 * c + 1];
    int chA = cA[wA], chB = cB[wB];
    float rx = r[2 * c], ry = r[2 * c + 1];
    float fwA = (float)wA, fwB = (float)wB, fcA = (float)chA, fcB = (float)chB;
    float sb = 0.f, db = 0.f, qb = 0.f;
#pragma unroll
    for (int o = 0; o < 4; o++) {
        float base = bg[o]
              + fwA * W[4  + o] + fcA * W[8  + o] + pA * W[16 + o]
              + fwB * W[24 + o] + fcB * W[28 + o] + pB * W[36 + o]
              + rx  * W[40 + o] + ry  * W[44 + o];
        sb += base * asrc[o];
        db += base * adst[o];
        qb += base * Wm[o];
    }
    *sb_o = sb * L2E; *db_o = db * L2E; *qb_o = qb;
    *chA_o = chA; *chB_o = chB;
}

// ---------------- fused scatter + sdq ----------------
// Blocks [0, SCATB): bucket scatter (1 edge/thread, atomics overlap with
// the streaming sdq blocks). Blocks [SCATB, SCATB+SDQB): s,q for 4 nodes.
__global__ __launch_bounds__(256) void k_work(
    const int* __restrict__ edges, const float* __restrict__ x,
    const int* __restrict__ c0, const int* __restrict__ c1, const int* __restrict__ c2,
    const int* __restrict__ g01, const int* __restrict__ g12, const int* __restrict__ g20,
    const float* __restrict__ r01, const float* __restrict__ r12, const float* __restrict__ r20,
    const float* __restrict__ W, const float* __restrict__ bg,
    const float* __restrict__ asrc, const float* __restrict__ adst,
    const float* __restrict__ Wm, const float* __restrict__ bm)
{
    int b = blockIdx.x;
    if (b < SCATB) {
        int e = b * 256 + threadIdx.x;
        if (e < NE) {
            int s = edges[e];
            int d = edges[NE + e];
            int p = atomicAdd(&g_cnt[d], 1);
            if (p < DEGCAP) g_csr[d * DEGCAP + p] = s * TT2;
        }
        return;
    }
    __shared__ float sh_sb[4], sh_qb[4], sh_cf[10];
    __shared__ int   sh_chA[4], sh_chB[4];
    int bb = b - SCATB;
    int tid = threadIdx.x;
    if (tid < 4) {
        float db;
        node_static(bb * 4 + tid, c0, c1, c2, g01, g12, g20, r01, r12, r20,
                    W, bg, asrc, adst, Wm,
                    &sh_sb[tid], &db, &sh_qb[tid], &sh_chA[tid], &sh_chB[tid]);
    } else if (tid == 4) {
        calc_coefs(W, asrc, adst, Wm, bm, sh_cf);
    }
    __syncthreads();

    int local = tid >> 6;          // node within block
    int tp    = tid & 63;
    int n = bb * 4 + local;
    const float2* x2 = (const float2*)x;
    float2 xA = __ldg(&x2[sh_chA[local] * TT2 + tp]);
    float2 xB = __ldg(&x2[sh_chB[local] * TT2 + tp]);
    float sb = sh_sb[local], qb = sh_qb[local];
    float cSA = sh_cf[0], cSB = sh_cf[1], cST = sh_cf[2];
    float cQA = sh_cf[6], cQB = sh_cf[7], cQT = sh_cf[8];
    float t0 = (float)(2 * tp), t1 = t0 + 1.f;

    float s0 = sb + xA.x * cSA + xB.x * cSB + t0 * cST;
    float s1 = sb + xA.y * cSA + xB.y * cSB + t1 * cST;
    float q0 = qb + xA.x * cQA + xB.x * cQB + t0 * cQT;
    float q1 = qb + xA.y * cQA + xB.y * cQB + t1 * cQT;

    g_sq4[n * TT2 + tp] = make_float4(s0, q0, s1, q1);
}

// ---------------- GAT aggregation (R7 online softmax, exp2 domain) ----------------
// Warp = node; lane owns ticks {2l, 2l+1, 64+2l, 65+2l}; 8 nodes/block.
__global__ __launch_bounds__(256) void k_agg(
    const float* __restrict__ x, float* __restrict__ out,
    const int* __restrict__ c0, const int* __restrict__ c1, const int* __restrict__ c2,
    const int* __restrict__ g01, const int* __restrict__ g12, const int* __restrict__ g20,
    const float* __restrict__ r01, const float* __restrict__ r12, const float* __restrict__ r20,
    const float* __restrict__ W, const float* __restrict__ bg,
    const float* __restrict__ asrc, const float* __restrict__ adst,
    const float* __restrict__ Wm, const float* __restrict__ bm)
{
    __shared__ float s_res[TT * 9];
    __shared__ float sh_db[8], sh_cf[10];
    __shared__ int   sh_chA[8], sh_chB[8];
    int tid  = threadIdx.x;
    int warp = tid >> 5, lane = tid & 31;
    int n0 = blockIdx.x * 8;

    if (tid < 8) {
        float sb, qb;
        node_static(n0 + tid, c0, c1, c2, g01, g12, g20, r01, r12, r20,
                    W, bg, asrc, adst, Wm,
                    &sb, &sh_db[tid], &qb, &sh_chA[tid], &sh_chB[tid]);
    } else if (tid == 8) {
        calc_coefs(W, asrc, adst, Wm, bm, sh_cf);
    }
    __syncthreads();

    int n  = n0 + warp;
    int deg = g_cnt[n];
    if (deg > DEGCAP) deg = DEGCAP;
    const int* row = g_csr + n * DEGCAP;
    float bmlp = sh_cf[9];
    float cDA = sh_cf[3], cDB = sh_cf[4], cDT = sh_cf[5];
    float dbv = sh_db[warp];
    int chA = sh_chA[warp], chB = sh_chB[warp];

    // dv for this lane's 4 ticks (scaled domain)
    const float2* x2 = (const float2*)x;
    float dv[4], m[4], den[4], acc[4];
#pragma unroll
    for (int k = 0; k < 2; k++) {
        float2 xA = x2[chA * TT2 + lane + 32 * k];
        float2 xB = x2[chB * TT2 + lane + 32 * k];
        float t0 = (float)(2 * (lane + 32 * k));
        dv[2 * k]     = dbv + xA.x * cDA + xB.x * cDB + t0 * cDT;
        dv[2 * k + 1] = dbv + xA.y * cDA + xB.y * cDB + (t0 + 1.f) * cDT;
    }
#pragma unroll
    for (int k = 0; k < 4; k++) { m[k] = -1e30f; den[k] = 0.f; acc[k] = 0.f; }

    int rv_next = (deg > 0) ? row[0] : 0;
    for (int j = 0; j < deg; j++) {
        int rv = rv_next;
        if (j + 1 < deg) rv_next = row[j + 1];
        float4 sq0 = g_sq4[rv + lane];        // ticks 2l, 2l+1
        float4 sq1 = g_sq4[rv + 32 + lane];   // ticks 64+2l, 65+2l
        float es[4] = { sq0.x, sq0.z, sq1.x, sq1.z };
        float qs[4] = { sq0.y, sq0.w, sq1.y, sq1.w };
#pragma unroll
        for (int k = 0; k < 4; k++) {
            float e = es[k] + dv[k];
            e = fmaxf(e, 0.2f * e);                 // leaky (scaled domain)
            float nm = fmaxf(m[k], e);
            float r = exp2f(m[k] - nm);             // independent MUFUs (R7 shape)
            float w = exp2f(e - nm);
            den[k] = fmaf(den[k], r, w);
            acc[k] = fmaf(acc[k], r, w * qs[k]);
            m[k] = nm;
        }
    }
    // ticks for k: 0->2l, 1->2l+1, 2->64+2l, 3->65+2l
#pragma unroll
    for (int k = 0; k < 4; k++) {
        int t = 2 * lane + (k & 1) + 64 * (k >> 1);
        float z = acc[k] / (den[k] + 1e-9f) + bmlp;
        s_res[t * 9 + warp] = 1.f / (1.f + __expf(-z));
    }
    __syncthreads();
#pragma unroll
    for (int p = 0; p < 4; p++) {
        int i = p * 256 + tid;
        int t = i >> 3, c = i & 7;
        out[t * NCROSS + n0 + c] = s_res[t * 9 + c];
    }
}

// ---------------- launch ----------------
extern "C" void kernel_launch(void* const* d_in, const int* in_sizes, int n_in,
                              void* d_out, int out_size)
{
    const float* x    = (const float*)d_in[0];
    const int*   c0   = (const int*)  d_in[1];
    const int*   c1   = (const int*)  d_in[2];
    const int*   c2   = (const int*)  d_in[3];
    const int*   g01  = (const int*)  d_in[4];
    const int*   g12  = (const int*)  d_in[5];
    const int*   g20  = (const int*)  d_in[6];
    const float* r01  = (const float*)d_in[7];
    const float* r12  = (const float*)d_in[8];
    const float* r20  = (const float*)d_in[9];
    const int*   edges= (const int*)  d_in[10];
    const float* Wg   = (const float*)d_in[11];
    const float* asrc = (const float*)d_in[12];
    const float* adst = (const float*)d_in[13];
    const float* bg   = (const float*)d_in[14];
    const float* Wm   = (const float*)d_in[15];
    const float* bm   = (const float*)d_in[16];
    float* out = (float*)d_out;

    void* cntp = nullptr;
    cudaGetSymbolAddress(&cntp, g_cnt);
    cudaMemsetAsync(cntp, 0, NCROSS * sizeof(int));

    k_work<<<SCATB + SDQB, 256>>>(edges, x, c0, c1, c2, g01, g12, g20,
                                  r01, r12, r20, Wg, bg, asrc, adst, Wm, bm);
    k_agg<<<NCROSS / 8, 256>>>(x, out, c0, c1, c2, g01, g12, g20,
                               r01, r12, r20, Wg, bg, asrc, adst, Wm, bm);
}

// round 15
// speedup vs baseline: 1.0577x; 1.0577x over previous
#include <cuda_runtime.h>
#include <math.h>

// Problem constants (fixed by the dataset)
#define TT      128
#define TT2     64
#define NCH     1536
#define NC0     10000
#define NCROSS  30000
#define NE      120000
#define DEGCAP  32            // P(Poisson(4) > 32) ~ 1e-22; safe fixed bucket
#define L2E     1.44269504088896f
#define SCATB   ((NE + 255) / 256)           // 469 scatter blocks (1 edge/thread)
#define SDQB    (NCROSS / 4)                 // 7500 sdq blocks (4 nodes/block)

// ---------------- scratch (static device allocations) ----------------
__device__ float4 g_sq4[NCROSS * TT2];     // [n][tp] = (s0,q0,s1,q1), s log2e-scaled
__device__ float4 g_aux[NCROSS];           // (dbase*, chA bits, chB bits, -) [* log2e]
__device__ int    g_cnt[NCROSS];
__device__ int    g_csr[NCROSS * DEGCAP];  // entries pre-multiplied by TT2
__device__ float  g_coef[12];              // dA dB dT bm (slots 3,4,5,9; d scaled)

// W rows (13x4 row-major): 0 sigA, 1 wireA, 2 chanA, 3 zero, 4 planeA,
// 5 sigB, 6 wireB, 7 chanB, 8 zero, 9 planeB, 10 ray_x, 11 ray_y, 12 tick
// coefs out[10]: sA sB sT dA dB dT qA qB qT bm   (s,d scaled by log2e)
__device__ __forceinline__ void calc_coefs(
    const float* __restrict__ W, const float* __restrict__ asrc,
    const float* __restrict__ adst, const float* __restrict__ Wm,
    const float* __restrict__ bm, float* out)
{
    float sA = 0, sB = 0, sT = 0, dA = 0, dB = 0, dT = 0, qA = 0, qB = 0, qT = 0;
#pragma unroll
    for (int o = 0; o < 4; o++) {
        float wA = W[o], wB = W[20 + o], wT = W[48 + o];
        sA += wA * asrc[o]; sB += wB * asrc[o]; sT += wT * asrc[o];
        dA += wA * adst[o]; dB += wB * adst[o]; dT += wT * adst[o];
        qA += wA * Wm[o];   qB += wB * Wm[o];   qT += wT * Wm[o];
    }
    out[0] = sA * L2E; out[1] = sB * L2E; out[2] = sT * L2E;
    out[3] = dA * L2E; out[4] = dB * L2E; out[5] = dT * L2E;
    out[6] = qA; out[7] = qB; out[8] = qT; out[9] = bm[0];
}

// Per-node static bases (sb, db scaled by log2e) + channels.
__device__ __forceinline__ void node_static(
    int i,
    const int* __restrict__ c0, const int* __restrict__ c1, const int* __restrict__ c2,
    const int* __restrict__ g01, const int* __restrict__ g12, const int* __restrict__ g20,
    const float* __restrict__ r01, const float* __restrict__ r12, const float* __restrict__ r20,
    const float* __restrict__ W, const float* __restrict__ bg,
    const float* __restrict__ asrc, const float* __restrict__ adst,
    const float* __restrict__ Wm,
    float* sb_o, float* db_o, float* qb_o, int* chA_o, int* chB_o)
{
    int p = i / NC0, c = i % NC0;
    const int* g; const float* r; const int* cA; const int* cB; float pA, pB;
    if (p == 0)      { g = g01; r = r01; cA = c0; cB = c1; pA = 0.f; pB = 1.f; }
    else if (p == 1) { g = g12; r = r12; cA = c1; cB = c2; pA = 1.f; pB = 2.f; }
    else             { g = g20; r = r20; cA = c2; cB = c0; pA = 2.f; pB = 0.f; }
    int wA = g[2 * c], wB = g[2 * c + 1];
    int chA = cA[wA], chB = cB[wB];
    float rx = r[2 * c], ry = r[2 * c + 1];
    float fwA = (float)wA, fwB = (float)wB, fcA = (float)chA, fcB = (float)chB;
    float sb = 0.f, db = 0.f, qb = 0.f;
#pragma unroll
    for (int o = 0; o < 4; o++) {
        float base = bg[o]
              + fwA * W[4  + o] + fcA * W[8  + o] + pA * W[16 + o]
              + fwB * W[24 + o] + fcB * W[28 + o] + pB * W[36 + o]
              + rx  * W[40 + o] + ry  * W[44 + o];
        sb += base * asrc[o];
        db += base * adst[o];
        qb += base * Wm[o];
    }
    *sb_o = sb * L2E; *db_o = db * L2E; *qb_o = qb;
    *chA_o = chA; *chB_o = chB;
}

// ---------------- fused scatter + sdq (+ aux/coef export for k_agg) ----------------
// Blocks [0, SCATB): bucket scatter (1 edge/thread). Blocks [SCATB, +SDQB):
// s,q for 4 nodes; also exports per-node (db, chA, chB) and (block 0) coefs.
__global__ __launch_bounds__(256) void k_work(
    const int* __restrict__ edges, const float* __restrict__ x,
    const int* __restrict__ c0, const int* __restrict__ c1, const int* __restrict__ c2,
    const int* __restrict__ g01, const int* __restrict__ g12, const int* __restrict__ g20,
    const float* __restrict__ r01, const float* __restrict__ r12, const float* __restrict__ r20,
    const float* __restrict__ W, const float* __restrict__ bg,
    const float* __restrict__ asrc, const float* __restrict__ adst,
    const float* __restrict__ Wm, const float* __restrict__ bm)
{
    int b = blockIdx.x;
    if (b < SCATB) {
        int e = b * 256 + threadIdx.x;
        if (e < NE) {
            int s = edges[e];
            int d = edges[NE + e];
            int p = atomicAdd(&g_cnt[d], 1);
            if (p < DEGCAP) g_csr[d * DEGCAP + p] = s * TT2;
        }
        return;
    }
    __shared__ float sh_sb[4], sh_qb[4], sh_cf[10];
    __shared__ int   sh_chA[4], sh_chB[4];
    int bb = b - SCATB;
    int tid = threadIdx.x;
    if (tid < 4) {
        float db;
        int n = bb * 4 + tid;
        node_static(n, c0, c1, c2, g01, g12, g20, r01, r12, r20,
                    W, bg, asrc, adst, Wm,
                    &sh_sb[tid], &db, &sh_qb[tid], &sh_chA[tid], &sh_chB[tid]);
        g_aux[n] = make_float4(db, __int_as_float(sh_chA[tid]),
                               __int_as_float(sh_chB[tid]), 0.f);
    } else if (tid == 4) {
        calc_coefs(W, asrc, adst, Wm, bm, sh_cf);
        if (bb == 0) {
            g_coef[3] = sh_cf[3]; g_coef[4] = sh_cf[4];
            g_coef[5] = sh_cf[5]; g_coef[9] = sh_cf[9];
        }
    }
    __syncthreads();

    int local = tid >> 6;          // node within block
    int tp    = tid & 63;
    int n = bb * 4 + local;
    const float2* x2 = (const float2*)x;
    float2 xA = __ldg(&x2[sh_chA[local] * TT2 + tp]);
    float2 xB = __ldg(&x2[sh_chB[local] * TT2 + tp]);
    float sb = sh_sb[local], qb = sh_qb[local];
    float cSA = sh_cf[0], cSB = sh_cf[1], cST = sh_cf[2];
    float cQA = sh_cf[6], cQB = sh_cf[7], cQT = sh_cf[8];
    float t0 = (float)(2 * tp), t1 = t0 + 1.f;

    float s0 = sb + xA.x * cSA + xB.x * cSB + t0 * cST;
    float s1 = sb + xA.y * cSA + xB.y * cSB + t1 * cST;
    float q0 = qb + xA.x * cQA + xB.x * cQB + t0 * cQT;
    float q1 = qb + xA.y * cQA + xB.y * cQB + t1 * cQT;

    g_sq4[n * TT2 + tp] = make_float4(s0, q0, s1, q1);
}

// ---------------- GAT aggregation (lean R12 shape; R7 online softmax) ----------------
// Warp = node; lane owns ticks {2l, 2l+1, 64+2l, 65+2l}; 8 nodes/block.
__global__ __launch_bounds__(256) void k_agg(const float* __restrict__ x,
                                             float* __restrict__ out)
{
    __shared__ float s_res[TT * 9];
    int tid  = threadIdx.x;
    int warp = tid >> 5, lane = tid & 31;
    int n0 = blockIdx.x * 8;
    int n  = n0 + warp;
    int deg = g_cnt[n];
    if (deg > DEGCAP) deg = DEGCAP;
    const int* row = g_csr + n * DEGCAP;
    float bmlp = g_coef[9];
    float cDA = g_coef[3], cDB = g_coef[4], cDT = g_coef[5];

    float4 aux = g_aux[n];
    float dbv = aux.x;
    int chA = __float_as_int(aux.y), chB = __float_as_int(aux.z);

    // dv for this lane's 4 ticks (scaled domain)
    const float2* x2 = (const float2*)x;
    float dv[4], m[4], den[4], acc[4];
#pragma unroll
    for (int k = 0; k < 2; k++) {
        float2 xA = x2[chA * TT2 + lane + 32 * k];
        float2 xB = x2[chB * TT2 + lane + 32 * k];
        float t0 = (float)(2 * (lane + 32 * k));
        dv[2 * k]     = dbv + xA.x * cDA + xB.x * cDB + t0 * cDT;
        dv[2 * k + 1] = dbv + xA.y * cDA + xB.y * cDB + (t0 + 1.f) * cDT;
    }
#pragma unroll
    for (int k = 0; k < 4; k++) { m[k] = -1e30f; den[k] = 0.f; acc[k] = 0.f; }

    int rv_next = (deg > 0) ? row[0] : 0;
    for (int j = 0; j < deg; j++) {
        int rv = rv_next;
        if (j + 1 < deg) rv_next = row[j + 1];
        float4 sq0 = g_sq4[rv + lane];        // ticks 2l, 2l+1
        float4 sq1 = g_sq4[rv + 32 + lane];   // ticks 64+2l, 65+2l
        float es[4] = { sq0.x, sq0.z, sq1.x, sq1.z };
        float qs[4] = { sq0.y, sq0.w, sq1.y, sq1.w };
#pragma unroll
        for (int k = 0; k < 4; k++) {
            float e = es[k] + dv[k];
            e = fmaxf(e, 0.2f * e);                 // leaky (scaled domain)
            float nm = fmaxf(m[k], e);
            float r = exp2f(m[k] - nm);             // independent MUFUs (R7 shape)
            float w = exp2f(e - nm);
            den[k] = fmaf(den[k], r, w);
            acc[k] = fmaf(acc[k], r, w * qs[k]);
            m[k] = nm;
        }
    }
    // ticks for k: 0->2l, 1->2l+1, 2->64+2l, 3->65+2l
#pragma unroll
    for (int k = 0; k < 4; k++) {
        int t = 2 * lane + (k & 1) + 64 * (k >> 1);
        float z = acc[k] / (den[k] + 1e-9f) + bmlp;
        s_res[t * 9 + warp] = 1.f / (1.f + __expf(-z));
    }
    __syncthreads();
#pragma unroll
    for (int p = 0; p < 4; p++) {
        int i = p * 256 + tid;
        int t = i >> 3, c = i & 7;
        out[t * NCROSS + n0 + c] = s_res[t * 9 + c];
    }
}

// ---------------- launch ----------------
extern "C" void kernel_launch(void* const* d_in, const int* in_sizes, int n_in,
                              void* d_out, int out_size)
{
    const float* x    = (const float*)d_in[0];
    const int*   c0   = (const int*)  d_in[1];
    const int*   c1   = (const int*)  d_in[2];
    const int*   c2   = (const int*)  d_in[3];
    const int*   g01  = (const int*)  d_in[4];
    const int*   g12  = (const int*)  d_in[5];
    const int*   g20  = (const int*)  d_in[6];
    const float* r01  = (const float*)d_in[7];
    const float* r12  = (const float*)d_in[8];
    const float* r20  = (const float*)d_in[9];
    const int*   edges= (const int*)  d_in[10];
    const float* Wg   = (const float*)d_in[11];
    const float* asrc = (const float*)d_in[12];
    const float* adst = (const float*)d_in[13];
    const float* bg   = (const float*)d_in[14];
    const float* Wm   = (const float*)d_in[15];
    const float* bm   = (const float*)d_in[16];
    float* out = (float*)d_out;

    void* cntp = nullptr;
    cudaGetSymbolAddress(&cntp, g_cnt);
    cudaMemsetAsync(cntp, 0, NCROSS * sizeof(int));

    k_work<<<SCATB + SDQB, 256>>>(edges, x, c0, c1, c2, g01, g12, g20,
                                  r01, r12, r20, Wg, bg, asrc, adst, Wm, bm);
    k_agg<<<NCROSS / 8, 256>>>(x, out);
}

// round 17
// speedup vs baseline: 1.1719x; 1.1080x over previous
#include <cuda_runtime.h>
#include <math.h>

// Problem constants (fixed by the dataset)
#define TT      128
#define TT2     64
#define NCH     1536
#define NC0     10000
#define NCROSS  30000
#define NE      120000
#define DEGCAP  32            // P(Poisson(4) > 32) ~ 1e-22; safe fixed bucket
#define L2E     1.44269504088896f
#define SCATB   ((NE + 255) / 256)           // 469 scatter blocks (1 edge/thread)
#define SDQB    (NCROSS / 16)                // 1875 sdq blocks (16 nodes/block)

// ---------------- scratch (static device allocations) ----------------
__device__ float4 g_sq4[NCROSS * TT2];     // float2 view: [n*128+t] = (s,q), s log2e-scaled
__device__ float4 g_aux[NCROSS];           // (dbase*, chA bits, chB bits, -) [* log2e]
__device__ int    g_cnt[NCROSS];
__device__ int    g_csr[NCROSS * DEGCAP];  // entries pre-multiplied by TT2
__device__ float  g_coef[12];              // dA dB dT bm (slots 3,4,5,9; d scaled)

// W rows (13x4 row-major): 0 sigA, 1 wireA, 2 chanA, 3 zero, 4 planeA,
// 5 sigB, 6 wireB, 7 chanB, 8 zero, 9 planeB, 10 ray_x, 11 ray_y, 12 tick
// coefs out[10]: sA sB sT dA dB dT qA qB qT bm   (s,d scaled by log2e)
__device__ __forceinline__ void calc_coefs(
    const float* __restrict__ W, const float* __restrict__ asrc,
    const float* __restrict__ adst, const float* __restrict__ Wm,
    const float* __restrict__ bm, float* out)
{
    float sA = 0, sB = 0, sT = 0, dA = 0, dB = 0, dT = 0, qA = 0, qB = 0, qT = 0;
#pragma unroll
    for (int o = 0; o < 4; o++) {
        float wA = W[o], wB = W[20 + o], wT = W[48 + o];
        sA += wA * asrc[o]; sB += wB * asrc[o]; sT += wT * asrc[o];
        dA += wA * adst[o]; dB += wB * adst[o]; dT += wT * adst[o];
        qA += wA * Wm[o];   qB += wB * Wm[o];   qT += wT * Wm[o];
    }
    out[0] = sA * L2E; out[1] = sB * L2E; out[2] = sT * L2E;
    out[3] = dA * L2E; out[4] = dB * L2E; out[5] = dT * L2E;
    out[6] = qA; out[7] = qB; out[8] = qT; out[9] = bm[0];
}

// Per-node static bases (sb, db scaled by log2e) + channels.
__device__ __forceinline__ void node_static(
    int i,
    const int* __restrict__ c0, const int* __restrict__ c1, const int* __restrict__ c2,
    const int* __restrict__ g01, const int* __restrict__ g12, const int* __restrict__ g20,
    const float* __restrict__ r01, const float* __restrict__ r12, const float* __restrict__ r20,
    const float* __restrict__ W, const float* __restrict__ bg,
    const float* __restrict__ asrc, const float* __restrict__ adst,
    const float* __restrict__ Wm,
    float* sb_o, float* db_o, float* qb_o, int* chA_o, int* chB_o)
{
    int p = i / NC0, c = i % NC0;
    const int* g; const float* r; const int* cA; const int* cB; float pA, pB;
    if (p == 0)      { g = g01; r = r01; cA = c0; cB = c1; pA = 0.f; pB = 1.f; }
    else if (p == 1) { g = g12; r = r12; cA = c1; cB = c2; pA = 1.f; pB = 2.f; }
    else             { g = g20; r = r20; cA = c2; cB = c0; pA = 2.f; pB = 0.f; }
    int wA = g[2 * c], wB = g[2 * c + 1];
    int chA = cA[wA], chB = cB[wB];
    float rx = r[2 * c], ry = r[2 * c + 1];
    float fwA = (float)wA, fwB = (float)wB, fcA = (float)chA, fcB = (float)chB;
    float sb = 0.f, db = 0.f, qb = 0.f;
#pragma unroll
    for (int o = 0; o < 4; o++) {
        float base = bg[o]
              + fwA * W[4  + o] + fcA * W[8  + o] + pA * W[16 + o]
              + fwB * W[24 + o] + fcB * W[28 + o] + pB * W[36 + o]
              + rx  * W[40 + o] + ry  * W[44 + o];
        sb += base * asrc[o];
        db += base * adst[o];
        qb += base * Wm[o];
    }
    *sb_o = sb * L2E; *db_o = db * L2E; *qb_o = qb;
    *chA_o = chA; *chB_o = chB;
}

// ---------------- fused scatter + sdq (+ aux/coef export for k_agg) ----------------
// Blocks [0, SCATB): bucket scatter (1 edge/thread). Blocks [SCATB, +SDQB):
// s,q for 16 nodes (16 threads/node, thread owns 8 ticks strided by 16).
__global__ __launch_bounds__(256) void k_work(
    const int* __restrict__ edges, const float* __restrict__ x,
    const int* __restrict__ c0, const int* __restrict__ c1, const int* __restrict__ c2,
    const int* __restrict__ g01, const int* __restrict__ g12, const int* __restrict__ g20,
    const float* __restrict__ r01, const float* __restrict__ r12, const float* __restrict__ r20,
    const float* __restrict__ W, const float* __restrict__ bg,
    const float* __restrict__ asrc, const float* __restrict__ adst,
    const float* __restrict__ Wm, const float* __restrict__ bm)
{
    int b = blockIdx.x;
    if (b < SCATB) {
        int e = b * 256 + threadIdx.x;
        if (e < NE) {
            int s = edges[e];
            int d = edges[NE + e];
            int p = atomicAdd(&g_cnt[d], 1);
            if (p < DEGCAP) g_csr[d * DEGCAP + p] = s * TT2;
        }
        return;
    }
    __shared__ float sh_sb[16], sh_qb[16], sh_cf[10];
    __shared__ int   sh_chA[16], sh_chB[16];
    int bb = b - SCATB;
    int tid = threadIdx.x;
    if (tid < 16) {
        float db;
        int n = bb * 16 + tid;
        node_static(n, c0, c1, c2, g01, g12, g20, r01, r12, r20,
                    W, bg, asrc, adst, Wm,
                    &sh_sb[tid], &db, &sh_qb[tid], &sh_chA[tid], &sh_chB[tid]);
        g_aux[n] = make_float4(db, __int_as_float(sh_chA[tid]),
                               __int_as_float(sh_chB[tid]), 0.f);
    } else if (tid == 16) {
        calc_coefs(W, asrc, adst, Wm, bm, sh_cf);
        if (bb == 0) {
            g_coef[3] = sh_cf[3]; g_coef[4] = sh_cf[4];
            g_coef[5] = sh_cf[5]; g_coef[9] = sh_cf[9];
        }
    }
    __syncthreads();

    int local = tid >> 4;          // node within block (0..15)
    int sub   = tid & 15;          // tick-group within node
    int n = bb * 16 + local;
    const float* xA_row = x + sh_chA[local] * TT;
    const float* xB_row = x + sh_chB[local] * TT;
    float sb = sh_sb[local], qb = sh_qb[local];
    float cSA = sh_cf[0], cSB = sh_cf[1], cST = sh_cf[2];
    float cQA = sh_cf[6], cQB = sh_cf[7], cQT = sh_cf[8];
    float2* sq2 = (float2*)g_sq4;
#pragma unroll
    for (int k = 0; k < 8; k++) {
        int t = sub + 16 * k;
        float xa = __ldg(&xA_row[t]);
        float xb = __ldg(&xB_row[t]);
        float tf = (float)t;
        float s = sb + xa * cSA + xb * cSB + tf * cST;
        float q = qb + xa * cQA + xb * cQB + tf * cQT;
        sq2[n * TT + t] = make_float2(s, q);
    }
}

// ---------------- GAT aggregation (lean R12/R15 shape; R7 online softmax) ----------------
// Warp = node; lane owns ticks {2l, 2l+1, 64+2l, 65+2l}; 8 nodes/block.
__global__ __launch_bounds__(256) void k_agg(const float* __restrict__ x,
                                             float* __restrict__ out)
{
    __shared__ float s_res[TT * 9];
    int tid  = threadIdx.x;
    int warp = tid >> 5, lane = tid & 31;
    int n0 = blockIdx.x * 8;
    int n  = n0 + warp;
    int deg = g_cnt[n];
    if (deg > DEGCAP) deg = DEGCAP;
    const int* row = g_csr + n * DEGCAP;
    float bmlp = g_coef[9];
    float cDA = g_coef[3], cDB = g_coef[4], cDT = g_coef[5];

    float4 aux = g_aux[n];
    float dbv = aux.x;
    int chA = __float_as_int(aux.y), chB = __float_as_int(aux.z);

    // dv for this lane's 4 ticks (scaled domain)
    const float2* x2 = (const float2*)x;
    float dv[4], m[4], den[4], acc[4];
#pragma unroll
    for (int k = 0; k < 2; k++) {
        float2 xA = x2[chA * TT2 + lane + 32 * k];
        float2 xB = x2[chB * TT2 + lane + 32 * k];
        float t0 = (float)(2 * (lane + 32 * k));
        dv[2 * k]     = dbv + xA.x * cDA + xB.x * cDB + t0 * cDT;
        dv[2 * k + 1] = dbv + xA.y * cDA + xB.y * cDB + (t0 + 1.f) * cDT;
    }
#pragma unroll
    for (int k = 0; k < 4; k++) { m[k] = -1e30f; den[k] = 0.f; acc[k] = 0.f; }

    int rv_next = (deg > 0) ? row[0] : 0;
    for (int j = 0; j < deg; j++) {
        int rv = rv_next;
        if (j + 1 < deg) rv_next = row[j + 1];
        float4 sq0 = g_sq4[rv + lane];        // ticks 2l, 2l+1
        float4 sq1 = g_sq4[rv + 32 + lane];   // ticks 64+2l, 65+2l
        float es[4] = { sq0.x, sq0.z, sq1.x, sq1.z };
        float qs[4] = { sq0.y, sq0.w, sq1.y, sq1.w };
#pragma unroll
        for (int k = 0; k < 4; k++) {
            float e = es[k] + dv[k];
            e = fmaxf(e, 0.2f * e);                 // leaky (scaled domain)
            float nm = fmaxf(m[k], e);
            float r = exp2f(m[k] - nm);             // independent MUFUs (R7 shape)
            float w = exp2f(e - nm);
            den[k] = fmaf(den[k], r, w);
            acc[k] = fmaf(acc[k], r, w * qs[k]);
            m[k] = nm;
        }
    }
    // ticks for k: 0->2l, 1->2l+1, 2->64+2l, 3->65+2l
#pragma unroll
    for (int k = 0; k < 4; k++) {
        int t = 2 * lane + (k & 1) + 64 * (k >> 1);
        float z = acc[k] / (den[k] + 1e-9f) + bmlp;
        s_res[t * 9 + warp] = 1.f / (1.f + __expf(-z));
    }
    __syncthreads();
#pragma unroll
    for (int p = 0; p < 4; p++) {
        int i = p * 256 + tid;
        int t = i >> 3, c = i & 7;
        out[t * NCROSS + n0 + c] = s_res[t * 9 + c];
    }
}

// ---------------- launch ----------------
extern "C" void kernel_launch(void* const* d_in, const int* in_sizes, int n_in,
                              void* d_out, int out_size)
{
    const float* x    = (const float*)d_in[0];
    const int*   c0   = (const int*)  d_in[1];
    const int*   c1   = (const int*)  d_in[2];
    const int*   c2   = (const int*)  d_in[3];
    const int*   g01  = (const int*)  d_in[4];
    const int*   g12  = (const int*)  d_in[5];
    const int*   g20  = (const int*)  d_in[6];
    const float* r01  = (const float*)d_in[7];
    const float* r12  = (const float*)d_in[8];
    const float* r20  = (const float*)d_in[9];
    const int*   edges= (const int*)  d_in[10];
    const float* Wg   = (const float*)d_in[11];
    const float* asrc = (const float*)d_in[12];
    const float* adst = (const float*)d_in[13];
    const float* bg   = (const float*)d_in[14];
    const float* Wm   = (const float*)d_in[15];
    const float* bm   = (const float*)d_in[16];
    float* out = (float*)d_out;

    void* cntp = nullptr;
    cudaGetSymbolAddress(&cntp, g_cnt);
    cudaMemsetAsync(cntp, 0, NCROSS * sizeof(int));

    k_work<<<SCATB + SDQB, 256>>>(edges, x, c0, c1, c2, g01, g12, g20,
                                  r01, r12, r20, Wg, bg, asrc, adst, Wm, bm);
    k_agg<<<NCROSS / 8, 256>>>(x, out);
}